// round 3
// baseline (speedup 1.0000x reference)
#include <cuda_runtime.h>
#include <math.h>

// Problem constants (fixed shapes from reference)
#define NB 2
#define NS 2048
#define ND 4096
#define NH 32
#define NHD 128
#define NAL 10

// Scratch: __device__ globals (allocation-free rule)
static __device__ float g_Q[(size_t)NB * NS * ND];       // 64 MB
static __device__ float g_K[(size_t)NB * NS * ND];       // 64 MB
static __device__ float g_V[(size_t)NB * NS * ND];       // 64 MB
static __device__ float g_AO[(size_t)NB * NS * ND];      // 64 MB
static __device__ float g_scores[(size_t)NB * NH * NS * NS]; // 1 GB
static __device__ float g_ak[NAL * ND];
static __device__ float g_av[NAL * ND];

// ---------------------------------------------------------------------------
// Tiled SGEMM: C = A @ B (or A @ B^T when TRANSB), fp32, 128x128 tile,
// BK=8, 256 threads, 8x8 per-thread micro-tile.
// Batched via blockIdx.z with (batch, head) decomposed strides.
// MODE 0: C = acc; MODE 1: C = acc*alpha + mask[row, col] (scores epilogue).
// All M, N multiples of 128; K multiple of 8 (true for every call site).
// ---------------------------------------------------------------------------
template <int MODE, bool TRANSB>
__global__ __launch_bounds__(256) void sgemm_kernel(
    const float* __restrict__ Abase, const float* __restrict__ Bbase,
    float* __restrict__ Cbase,
    int M, int N, int K, int lda, int ldb, int ldc, int Hdiv,
    long long sAb, long long sAh, long long sBb, long long sBh,
    long long sCb, long long sCh,
    float alpha, const float* __restrict__ mask, int ldm)
{
    __shared__ __align__(16) float As[8][128];
    __shared__ __align__(16) float Bs[8][128];

    const int z  = blockIdx.z;
    const int zb = z / Hdiv;
    const int zh = z % Hdiv;
    const float* A = Abase + zb * sAb + zh * sAh;
    const float* Bm = Bbase + zb * sBb + zh * sBh;
    float* C = Cbase + zb * sCb + zh * sCh;

    const int t  = threadIdx.x;
    const int bm = blockIdx.y * 128;
    const int bn = blockIdx.x * 128;

    // Loader indices
    const int lrow = t >> 1;          // 0..127
    const int lcol = (t & 1) * 4;     // 0 or 4
    const int brow = t >> 5;          // 0..7
    const int bcol = (t & 31) * 4;    // 0..124

    // Compute-thread indices
    const int tx = t & 15;
    const int ty = t >> 4;

    float acc[8][8];
#pragma unroll
    for (int i = 0; i < 8; i++)
#pragma unroll
        for (int j = 0; j < 8; j++) acc[i][j] = 0.0f;

    for (int kk = 0; kk < K; kk += 8) {
        // A tile (transpose into As[k][m])
        float4 a4 = *(const float4*)(A + (long long)(bm + lrow) * lda + kk + lcol);
        As[lcol + 0][lrow] = a4.x;
        As[lcol + 1][lrow] = a4.y;
        As[lcol + 2][lrow] = a4.z;
        As[lcol + 3][lrow] = a4.w;

        if (TRANSB) {
            // B is [N][K] row-major (e.g. K-matrix for Q K^T); transpose load.
            float4 b4 = *(const float4*)(Bm + (long long)(bn + lrow) * ldb + kk + lcol);
            Bs[lcol + 0][lrow] = b4.x;
            Bs[lcol + 1][lrow] = b4.y;
            Bs[lcol + 2][lrow] = b4.z;
            Bs[lcol + 3][lrow] = b4.w;
        } else {
            *(float4*)(&Bs[brow][bcol]) =
                *(const float4*)(Bm + (long long)(kk + brow) * ldb + bn + bcol);
        }
        __syncthreads();

#pragma unroll
        for (int k = 0; k < 8; k++) {
            float a[8], b[8];
            *(float4*)(a)     = *(const float4*)(&As[k][ty * 8]);
            *(float4*)(a + 4) = *(const float4*)(&As[k][ty * 8 + 4]);
            *(float4*)(b)     = *(const float4*)(&Bs[k][tx * 8]);
            *(float4*)(b + 4) = *(const float4*)(&Bs[k][tx * 8 + 4]);
#pragma unroll
            for (int i = 0; i < 8; i++)
#pragma unroll
                for (int j = 0; j < 8; j++)
                    acc[i][j] = fmaf(a[i], b[j], acc[i][j]);
        }
        __syncthreads();
    }

#pragma unroll
    for (int i = 0; i < 8; i++) {
        const long long row = bm + ty * 8 + i;
        float* crow = C + row * (long long)ldc + bn + tx * 8;
        float vals[8];
#pragma unroll
        for (int j = 0; j < 8; j++) vals[j] = acc[i][j];
        if (MODE == 1) {
            const float* mrow = mask + row * (long long)ldm + bn + tx * 8;
            float4 m0 = *(const float4*)(mrow);
            float4 m1 = *(const float4*)(mrow + 4);
            vals[0] = vals[0] * alpha + m0.x;
            vals[1] = vals[1] * alpha + m0.y;
            vals[2] = vals[2] * alpha + m0.z;
            vals[3] = vals[3] * alpha + m0.w;
            vals[4] = vals[4] * alpha + m1.x;
            vals[5] = vals[5] * alpha + m1.y;
            vals[6] = vals[6] * alpha + m1.z;
            vals[7] = vals[7] * alpha + m1.w;
        }
        *(float4*)(crow)     = make_float4(vals[0], vals[1], vals[2], vals[3]);
        *(float4*)(crow + 4) = make_float4(vals[4], vals[5], vals[6], vals[7]);
    }
}

// ---------------------------------------------------------------------------
// RoPE in-place on Q and K. One thread per (b,s,h,d2) pair.
// ---------------------------------------------------------------------------
__global__ void rope_qk_kernel(float* __restrict__ Q, float* __restrict__ K,
                               const float* __restrict__ cosT,
                               const float* __restrict__ sinT)
{
    long long idx = (long long)blockIdx.x * blockDim.x + threadIdx.x;
    const long long total = (long long)NB * NS * NH * (NHD / 2);
    if (idx >= total) return;
    int d2 = (int)(idx & (NHD / 2 - 1));   // 0..63
    long long r = idx >> 6;
    int h = (int)(r & (NH - 1));           // 0..31
    r >>= 5;
    int s = (int)(r & (NS - 1));           // 0..2047
    int b = (int)(r >> 11);

    float c  = cosT[s * (NHD / 2) + d2];
    float sn = sinT[s * (NHD / 2) + d2];
    long long off = ((((long long)b * NS + s) * NH + h) * NHD) + 2 * d2;

    float2 q = *(float2*)(Q + off);
    float2 k = *(float2*)(K + off);
    float2 qo, ko;
    qo.x = q.x * c - q.y * sn;
    qo.y = q.x * sn + q.y * c;
    ko.x = k.x * c - k.y * sn;
    ko.y = k.x * sn + k.y * c;
    *(float2*)(Q + off) = qo;
    *(float2*)(K + off) = ko;
}

// ---------------------------------------------------------------------------
// Adapter projections: ak = adapter @ wk, av = adapter @ wv.
// adapter: [AL][K]. One block per 256-wide N chunk; accumulate all AL rows.
// ---------------------------------------------------------------------------
__global__ void adapter_gemm_kernel(const float* __restrict__ adapter,
                                    const float* __restrict__ Wk,
                                    const float* __restrict__ Wv,
                                    float* __restrict__ ak,
                                    float* __restrict__ av)
{
    const int n = blockIdx.x * 256 + threadIdx.x;
    __shared__ float a_sh[NAL][64];
    float accK[NAL], accV[NAL];
#pragma unroll
    for (int r = 0; r < NAL; r++) { accK[r] = 0.f; accV[r] = 0.f; }

    for (int k0 = 0; k0 < ND; k0 += 64) {
        for (int idx = threadIdx.x; idx < NAL * 64; idx += 256) {
            int r = idx / 64, c = idx % 64;
            a_sh[r][c] = adapter[r * ND + k0 + c];
        }
        __syncthreads();
        for (int kc = 0; kc < 64; kc++) {
            float bk = Wk[(long long)(k0 + kc) * ND + n];
            float bv = Wv[(long long)(k0 + kc) * ND + n];
#pragma unroll
            for (int r = 0; r < NAL; r++) {
                accK[r] = fmaf(a_sh[r][kc], bk, accK[r]);
                accV[r] = fmaf(a_sh[r][kc], bv, accV[r]);
            }
        }
        __syncthreads();
    }
#pragma unroll
    for (int r = 0; r < NAL; r++) {
        ak[r * ND + n] = accK[r];
        av[r * ND + n] = accV[r];
    }
}

// ---------------------------------------------------------------------------
// Row softmax over the score matrix. One block (256 threads) per row of S.
// Single read + single write (values cached in registers).
// ---------------------------------------------------------------------------
__global__ void softmax_rows_kernel(float* __restrict__ sc)
{
    long long row = blockIdx.x;
    float* p = sc + row * (long long)NS;
    const int t = threadIdx.x;

    float v[8];
#pragma unroll
    for (int i = 0; i < 8; i++) v[i] = p[t + i * 256];

    float m = -1e30f;
#pragma unroll
    for (int i = 0; i < 8; i++) m = fmaxf(m, v[i]);

    __shared__ float red[256];
    red[t] = m;
    __syncthreads();
    for (int s = 128; s > 0; s >>= 1) {
        if (t < s) red[t] = fmaxf(red[t], red[t + s]);
        __syncthreads();
    }
    m = red[0];
    __syncthreads();

    float sum = 0.f;
#pragma unroll
    for (int i = 0; i < 8; i++) {
        v[i] = __expf(v[i] - m);
        sum += v[i];
    }
    red[t] = sum;
    __syncthreads();
    for (int s = 128; s > 0; s >>= 1) {
        if (t < s) red[t] += red[t + s];
        __syncthreads();
    }
    const float inv = 1.0f / red[0];
#pragma unroll
    for (int i = 0; i < 8; i++) p[t + i * 256] = v[i] * inv;
}

// ---------------------------------------------------------------------------
// Adapter attention add: AO[b,q,h,:] += gate[h] * softmax(q . ak^T / sqrt(HD)) @ av
// One warp per query row. 8 warps per block.
// ---------------------------------------------------------------------------
__global__ void adapter_attn_kernel(float* __restrict__ AO,
                                    const float* __restrict__ Q,
                                    const float* __restrict__ ak,
                                    const float* __restrict__ av,
                                    const float* __restrict__ gate)
{
    const int h = blockIdx.y;
    const int b = blockIdx.z;
    const int lane = threadIdx.x & 31;
    const int w = threadIdx.x >> 5;
    const int q = blockIdx.x * 8 + w;
    const float inv_sqrt = 0.08838834764831845f; // 1/sqrt(128)

    const float* qp = Q + (((long long)(b * NS + q)) * NH + h) * NHD;
    float qv[4];
#pragma unroll
    for (int i = 0; i < 4; i++) qv[i] = qp[lane + 32 * i];

    float sc[NAL];
#pragma unroll
    for (int j = 0; j < NAL; j++) {
        const float* akp = ak + j * ND + h * NHD;
        float s = 0.f;
#pragma unroll
        for (int i = 0; i < 4; i++) s = fmaf(qv[i], akp[lane + 32 * i], s);
#pragma unroll
        for (int off = 16; off > 0; off >>= 1)
            s += __shfl_xor_sync(0xFFFFFFFFu, s, off);
        sc[j] = s * inv_sqrt;
    }

    float m = sc[0];
#pragma unroll
    for (int j = 1; j < NAL; j++) m = fmaxf(m, sc[j]);
    float sum = 0.f;
#pragma unroll
    for (int j = 0; j < NAL; j++) {
        sc[j] = __expf(sc[j] - m);
        sum += sc[j];
    }
    const float g = gate[h] / sum;

    float o[4] = {0.f, 0.f, 0.f, 0.f};
#pragma unroll
    for (int j = 0; j < NAL; j++) {
        const float* avp = av + j * ND + h * NHD;
#pragma unroll
        for (int i = 0; i < 4; i++) o[i] = fmaf(sc[j], avp[lane + 32 * i], o[i]);
    }

    float* aop = AO + (((long long)(b * NS + q)) * NH + h) * NHD;
#pragma unroll
    for (int i = 0; i < 4; i++) aop[lane + 32 * i] += g * o[i];
}

// ---------------------------------------------------------------------------
// Launch sequence (graph-capturable: kernel launches only).
// Inputs (metadata order): x, cos, sin, mask, wq, wk, wv, wo, gate, adapter,
// random_init (always 0 -> gated-adapter branch).
// ---------------------------------------------------------------------------
extern "C" void kernel_launch(void* const* d_in, const int* in_sizes, int n_in,
                              void* d_out, int out_size)
{
    const float* x       = (const float*)d_in[0];
    const float* cosT    = (const float*)d_in[1];
    const float* sinT    = (const float*)d_in[2];
    const float* mask    = (const float*)d_in[3];
    const float* wq      = (const float*)d_in[4];
    const float* wk      = (const float*)d_in[5];
    const float* wv      = (const float*)d_in[6];
    const float* wo      = (const float*)d_in[7];
    const float* gate    = (const float*)d_in[8];
    const float* adapter = (const float*)d_in[9];
    float* out = (float*)d_out;

    float *Qp, *Kp, *Vp, *AOp, *Sc, *akp, *avp;
    cudaGetSymbolAddress((void**)&Qp, g_Q);
    cudaGetSymbolAddress((void**)&Kp, g_K);
    cudaGetSymbolAddress((void**)&Vp, g_V);
    cudaGetSymbolAddress((void**)&AOp, g_AO);
    cudaGetSymbolAddress((void**)&Sc, g_scores);
    cudaGetSymbolAddress((void**)&akp, g_ak);
    cudaGetSymbolAddress((void**)&avp, g_av);

    const float inv_sqrt = 0.08838834764831845f; // 1/sqrt(HD)
    dim3 blk(256);

    // 1-3. Q/K/V projections: (B*S, D) = (B*S, D) @ (D, D)
    {
        dim3 g(ND / 128, (NB * NS) / 128, 1);
        sgemm_kernel<0, false><<<g, blk>>>(x, wq, Qp, NB * NS, ND, ND, ND, ND, ND,
                                           1, 0, 0, 0, 0, 0, 0, 1.f, nullptr, 0);
        sgemm_kernel<0, false><<<g, blk>>>(x, wk, Kp, NB * NS, ND, ND, ND, ND, ND,
                                           1, 0, 0, 0, 0, 0, 0, 1.f, nullptr, 0);
        sgemm_kernel<0, false><<<g, blk>>>(x, wv, Vp, NB * NS, ND, ND, ND, ND, ND,
                                           1, 0, 0, 0, 0, 0, 0, 1.f, nullptr, 0);
    }

    // 4. RoPE on Q and K (in place)
    {
        const long long total = (long long)NB * NS * NH * (NHD / 2);
        rope_qk_kernel<<<(unsigned)((total + 255) / 256), 256>>>(Qp, Kp, cosT, sinT);
    }

    // 5. Adapter projections (no RoPE)
    adapter_gemm_kernel<<<ND / 256, 256>>>(adapter, wk, wv, akp, avp);

    // 6. Scores: per (b,h): S[q,j] = (Q . K^T) * inv_sqrt + mask[q,j]
    {
        dim3 g(NS / 128, NS / 128, NB * NH);
        sgemm_kernel<1, true><<<g, blk>>>(
            Qp, Kp, Sc, NS, NS, NHD, ND, ND, NS, NH,
            (long long)NS * ND, (long long)NHD,
            (long long)NS * ND, (long long)NHD,
            (long long)NH * NS * NS, (long long)NS * NS,
            inv_sqrt, mask, NS);
    }

    // 7. Softmax rows
    softmax_rows_kernel<<<NB * NH * NS, 256>>>(Sc);

    // 8. AO = P @ V per (b,h)
    {
        dim3 g(NHD / 128, NS / 128, NB * NH);
        sgemm_kernel<0, false><<<g, blk>>>(
            Sc, Vp, AOp, NS, NHD, NS, NS, ND, ND, NH,
            (long long)NH * NS * NS, (long long)NS * NS,
            (long long)NS * ND, (long long)NHD,
            (long long)NS * ND, (long long)NHD,
            1.f, nullptr, 0);
    }

    // 9. Adapter attention add (gated)
    adapter_attn_kernel<<<dim3(NS / 8, NH, NB), 256>>>(AOp, Qp, akp, avp, gate);

    // 10. Output projection: out = AO @ wo
    {
        dim3 g(ND / 128, (NB * NS) / 128, 1);
        sgemm_kernel<0, false><<<g, blk>>>(AOp, wo, out, NB * NS, ND, ND, ND, ND, ND,
                                           1, 0, 0, 0, 0, 0, 0, 1.f, nullptr, 0);
    }
}

// round 5
// speedup vs baseline: 2.2168x; 2.2168x over previous
#include <cuda_runtime.h>
#include <cuda_bf16.h>
#include <math.h>
#include <stdint.h>

// Problem constants (fixed shapes)
#define NB 2
#define NS 2048
#define ND 4096
#define NH 32
#define NHD 128
#define NAL 10

// ---------------------------------------------------------------------------
// Scratch (__device__ globals — allocation-free rule)
// ---------------------------------------------------------------------------
static __device__ __align__(256) float g_Q[(size_t)NB * NS * ND];        // fp32 (rope + adapter attn)
static __device__ __align__(256) float g_K[(size_t)NB * NS * ND];
static __device__ __align__(256) float g_AO[(size_t)NB * NS * ND];
static __device__ __align__(256) float g_scores[(size_t)NB * NH * NS * NS]; // 1 GB fp32 logits
static __device__ float g_ak[NAL * ND];
static __device__ float g_av[NAL * ND];

// bf16 hi/lo split operands
static __device__ __align__(256) __nv_bfloat16 g_xh[(size_t)NB * NS * ND];
static __device__ __align__(256) __nv_bfloat16 g_xl[(size_t)NB * NS * ND];
static __device__ __align__(256) __nv_bfloat16 g_Qh[(size_t)NB * NS * ND];
static __device__ __align__(256) __nv_bfloat16 g_Ql[(size_t)NB * NS * ND];
static __device__ __align__(256) __nv_bfloat16 g_Kh[(size_t)NB * NS * ND];
static __device__ __align__(256) __nv_bfloat16 g_Kl[(size_t)NB * NS * ND];
static __device__ __align__(256) __nv_bfloat16 g_Vth[(size_t)NB * NS * ND]; // V^T per head: [b][h][d][s]
static __device__ __align__(256) __nv_bfloat16 g_Vtl[(size_t)NB * NS * ND];
static __device__ __align__(256) __nv_bfloat16 g_Ph[(size_t)NB * NH * NS * NS];
static __device__ __align__(256) __nv_bfloat16 g_Pl[(size_t)NB * NH * NS * NS];
static __device__ __align__(256) __nv_bfloat16 g_AOh[(size_t)NB * NS * ND];
static __device__ __align__(256) __nv_bfloat16 g_AOl[(size_t)NB * NS * ND];
// Transposed weights [n][k] bf16 hi/lo
static __device__ __align__(256) __nv_bfloat16 g_wqh[(size_t)ND * ND];
static __device__ __align__(256) __nv_bfloat16 g_wql[(size_t)ND * ND];
static __device__ __align__(256) __nv_bfloat16 g_wkh[(size_t)ND * ND];
static __device__ __align__(256) __nv_bfloat16 g_wkl[(size_t)ND * ND];
static __device__ __align__(256) __nv_bfloat16 g_wvh[(size_t)ND * ND];
static __device__ __align__(256) __nv_bfloat16 g_wvl[(size_t)ND * ND];
static __device__ __align__(256) __nv_bfloat16 g_woh[(size_t)ND * ND];
static __device__ __align__(256) __nv_bfloat16 g_wol[(size_t)ND * ND];

// ---------------------------------------------------------------------------
// Small device helpers
// ---------------------------------------------------------------------------
__device__ __forceinline__ void split2(float v, __nv_bfloat16& h, __nv_bfloat16& l) {
    h = __float2bfloat16(v);
    l = __float2bfloat16(v - __bfloat162float(h));
}

__device__ __forceinline__ void cpasync16(uint32_t dst, const void* src) {
    asm volatile("cp.async.cg.shared.global [%0], [%1], 16;\n" :: "r"(dst), "l"(src));
}
__device__ __forceinline__ void cp_commit() {
    asm volatile("cp.async.commit_group;\n" ::: "memory");
}
__device__ __forceinline__ void cp_wait0() {
    asm volatile("cp.async.wait_group 0;\n" ::: "memory");
}
__device__ __forceinline__ void ldsm4(uint32_t* r, uint32_t addr) {
    asm volatile("ldmatrix.sync.aligned.m8n8.x4.shared.b16 {%0,%1,%2,%3}, [%4];\n"
                 : "=r"(r[0]), "=r"(r[1]), "=r"(r[2]), "=r"(r[3]) : "r"(addr));
}
__device__ __forceinline__ void mma16816(float* c, const uint32_t* a, const uint32_t* b) {
    asm volatile(
        "mma.sync.aligned.m16n8k16.row.col.f32.bf16.bf16.f32 "
        "{%0,%1,%2,%3},{%4,%5,%6,%7},{%8,%9},{%0,%1,%2,%3};\n"
        : "+f"(c[0]), "+f"(c[1]), "+f"(c[2]), "+f"(c[3])
        : "r"(a[0]), "r"(a[1]), "r"(a[2]), "r"(a[3]), "r"(b[0]), "r"(b[1]));
}

// ---------------------------------------------------------------------------
// Split-bf16 tensor-core GEMM.
// C[m][n] = sum_k A[m][k] * B[n][k]   (B always "[n][k]" row-major w/ ldb)
// A,B given as bf16 hi/lo pairs. Accumulate fp32 via 3 bf16 MMAs per product.
// CTA tile 128x128, BK=16, 8 warps (2x4), warp tile 64x32.
// EPI 0: C fp32.  EPI 1: C = acc*alpha + mask (scores).  EPI 2: write V^T hi/lo.
// ---------------------------------------------------------------------------
#define BM 128
#define BN 128
#define BK 16

template <int EPI>
__global__ __launch_bounds__(256) void mma_gemm(
    const __nv_bfloat16* __restrict__ Ah, const __nv_bfloat16* __restrict__ Al,
    const __nv_bfloat16* __restrict__ Bh, const __nv_bfloat16* __restrict__ Bl,
    float* __restrict__ C,
    int K, int lda, int ldb, int ldc, int Hdiv,
    long long sAb, long long sAh_, long long sBb, long long sBh_,
    long long sCb, long long sCh_,
    float alpha, const float* __restrict__ mask,
    __nv_bfloat16* __restrict__ Chi, __nv_bfloat16* __restrict__ Clo)
{
    // Shared: A buffers [stage][p][128][16] then B buffers. 32 KB total.
    __shared__ __align__(16) __nv_bfloat16 sm[16384];

    const int t = threadIdx.x;
    const int lane = t & 31;
    const int wid = t >> 5;
    const int warp_m = wid >> 2;   // 0..1
    const int warp_n = wid & 3;    // 0..3

    const int z = blockIdx.z;
    const int zb = z / Hdiv;
    const int zh = z % Hdiv;
    const __nv_bfloat16* pAh = Ah + zb * sAb + zh * sAh_;
    const __nv_bfloat16* pAl = Al + zb * sAb + zh * sAh_;
    const __nv_bfloat16* pBh = Bh + zb * sBb + zh * sBh_;
    const __nv_bfloat16* pBl = Bl + zb * sBb + zh * sBh_;
    float* pC = C + zb * sCb + zh * sCh_;

    const int bm = blockIdx.y * BM;
    const int bn = blockIdx.x * BN;

    // Loader: 256 threads -> 128 rows x 2 halves of 8 bf16 (16B)
    const int lrow = t >> 1;
    const int lhalf = (t & 1) * 8;
    const __nv_bfloat16* gAh = pAh + (long long)(bm + lrow) * lda + lhalf;
    const __nv_bfloat16* gAl = pAl + (long long)(bm + lrow) * lda + lhalf;
    const __nv_bfloat16* gBh = pBh + (long long)(bn + lrow) * ldb + lhalf;
    const __nv_bfloat16* gBl = pBl + (long long)(bn + lrow) * ldb + lhalf;

    const uint32_t smem0 = (uint32_t)__cvta_generic_to_shared(sm);
    const uint32_t ldst = (uint32_t)((lrow * 16 + lhalf) * 2);

    // ldmatrix per-lane offsets (row stride 32B)
    const int rA = lane & 15;
    const int cA = (lane >> 4) * 8;
    const uint32_t aoff = (uint32_t)((rA * 16 + cA) * 2);
    const int rB = (lane & 7) | ((lane & 16) >> 1);
    const int cB = (lane & 8);
    const uint32_t boff = (uint32_t)((rB * 16 + cB) * 2);

    float c[4][4][4];
#pragma unroll
    for (int i = 0; i < 4; i++)
#pragma unroll
        for (int j = 0; j < 4; j++)
#pragma unroll
            for (int r = 0; r < 4; r++) c[i][j][r] = 0.0f;

    const int T = K / BK;

    // prefetch stage 0
    {
        uint32_t da = smem0 + ldst;              // buf0, A hi
        cpasync16(da, gAh);
        cpasync16(da + 4096, gAl);               // A lo (+2048 elems)
        uint32_t db = smem0 + 16384 + ldst;      // buf0, B hi
        cpasync16(db, gBh);
        cpasync16(db + 4096, gBl);
        cp_commit();
    }

    for (int s = 0; s < T; s++) {
        cp_wait0();
        __syncthreads();

        if (s + 1 < T) {
            const int kk = (s + 1) * BK;
            const int buf = (s + 1) & 1;
            uint32_t da = smem0 + (uint32_t)(buf * 8192) + ldst;
            cpasync16(da, gAh + kk);
            cpasync16(da + 4096, gAl + kk);
            uint32_t db = smem0 + 16384 + (uint32_t)(buf * 8192) + ldst;
            cpasync16(db, gBh + kk);
            cpasync16(db + 4096, gBl + kk);
            cp_commit();
        }

        const int buf = s & 1;
        const uint32_t aH = smem0 + (uint32_t)(buf * 8192) + (uint32_t)(warp_m * 64 * 32) + aoff;
        const uint32_t aL = aH + 4096;
        const uint32_t bH = smem0 + 16384 + (uint32_t)(buf * 8192) + (uint32_t)(warp_n * 32 * 32) + boff;
        const uint32_t bL = bH + 4096;

        uint32_t ah[4][4], al_[4][4], bh[2][4], bl[2][4];
#pragma unroll
        for (int mf = 0; mf < 4; mf++) ldsm4(ah[mf], aH + mf * 512);
#pragma unroll
        for (int mf = 0; mf < 4; mf++) ldsm4(al_[mf], aL + mf * 512);
#pragma unroll
        for (int nb = 0; nb < 2; nb++) ldsm4(bh[nb], bH + nb * 512);
#pragma unroll
        for (int nb = 0; nb < 2; nb++) ldsm4(bl[nb], bL + nb * 512);

        // pass 1: Ahi * Bhi
#pragma unroll
        for (int mf = 0; mf < 4; mf++)
#pragma unroll
            for (int nf = 0; nf < 4; nf++)
                mma16816(c[mf][nf], ah[mf], &bh[nf >> 1][(nf & 1) * 2]);
        // pass 2: Ahi * Blo
#pragma unroll
        for (int mf = 0; mf < 4; mf++)
#pragma unroll
            for (int nf = 0; nf < 4; nf++)
                mma16816(c[mf][nf], ah[mf], &bl[nf >> 1][(nf & 1) * 2]);
        // pass 3: Alo * Bhi
#pragma unroll
        for (int mf = 0; mf < 4; mf++)
#pragma unroll
            for (int nf = 0; nf < 4; nf++)
                mma16816(c[mf][nf], al_[mf], &bh[nf >> 1][(nf & 1) * 2]);

        __syncthreads();
    }

    // Epilogue
    const int gq = lane >> 2;
    const int tg = lane & 3;
#pragma unroll
    for (int mf = 0; mf < 4; mf++) {
#pragma unroll
        for (int nf = 0; nf < 4; nf++) {
            const int r0 = bm + warp_m * 64 + mf * 16 + gq;
            const int c0 = bn + warp_n * 32 + nf * 8 + tg * 2;
            float* cc = c[mf][nf];
            if (EPI == 0) {
                *(float2*)&pC[(long long)r0 * ldc + c0] = make_float2(cc[0], cc[1]);
                *(float2*)&pC[(long long)(r0 + 8) * ldc + c0] = make_float2(cc[2], cc[3]);
            } else if (EPI == 1) {
                float2 m0 = *(const float2*)&mask[(long long)r0 * NS + c0];
                float2 m1 = *(const float2*)&mask[(long long)(r0 + 8) * NS + c0];
                *(float2*)&pC[(long long)r0 * ldc + c0] =
                    make_float2(cc[0] * alpha + m0.x, cc[1] * alpha + m0.y);
                *(float2*)&pC[(long long)(r0 + 8) * ldc + c0] =
                    make_float2(cc[2] * alpha + m1.x, cc[3] * alpha + m1.y);
            } else { // EPI == 2: V^T hi/lo:  Vt[((b*NH+h)*NHD+dc)*NS + s]
#pragma unroll
                for (int q = 0; q < 4; q++) {
                    const int m = r0 + (q >> 1) * 8;      // token
                    const int n = c0 + (q & 1);           // out channel
                    const int b = m >> 11, sdx = m & 2047;
                    const int h = n >> 7, dc = n & 127;
                    const long long idx =
                        (((long long)(b * NH + h)) * NHD + dc) * NS + sdx;
                    __nv_bfloat16 hb, lb;
                    split2(cc[q], hb, lb);
                    Chi[idx] = hb;
                    Clo[idx] = lb;
                }
            }
        }
    }
}

// ---------------------------------------------------------------------------
// Elementwise fp32 -> bf16 hi/lo split (vectorized by 4)
// ---------------------------------------------------------------------------
__global__ void split_kernel(const float* __restrict__ src,
                             __nv_bfloat16* __restrict__ h,
                             __nv_bfloat16* __restrict__ l, long long n)
{
    long long i = ((long long)blockIdx.x * blockDim.x + threadIdx.x) * 4;
    if (i >= n) return;
    float4 v = *(const float4*)(src + i);
    __nv_bfloat16 hh[4], ll[4];
    split2(v.x, hh[0], ll[0]);
    split2(v.y, hh[1], ll[1]);
    split2(v.z, hh[2], ll[2]);
    split2(v.w, hh[3], ll[3]);
#pragma unroll
    for (int k = 0; k < 4; k++) { h[i + k] = hh[k]; l[i + k] = ll[k]; }
}

// ---------------------------------------------------------------------------
// Weight transpose + split: Wt[n][k] = W[k][n], bf16 hi/lo
// ---------------------------------------------------------------------------
__global__ void wsplit_t_kernel(const float* __restrict__ W,
                                __nv_bfloat16* __restrict__ Th,
                                __nv_bfloat16* __restrict__ Tl)
{
    __shared__ float tile[32][33];
    const int n0 = blockIdx.x * 32, k0 = blockIdx.y * 32;
    const int tx = threadIdx.x, ty = threadIdx.y;
#pragma unroll
    for (int i = 0; i < 4; i++)
        tile[ty + 8 * i][tx] = W[(long long)(k0 + ty + 8 * i) * ND + n0 + tx];
    __syncthreads();
#pragma unroll
    for (int i = 0; i < 4; i++) {
        float v = tile[tx][ty + 8 * i];
        long long o = (long long)(n0 + ty + 8 * i) * ND + k0 + tx;
        __nv_bfloat16 hb, lb;
        split2(v, hb, lb);
        Th[o] = hb;
        Tl[o] = lb;
    }
}

// ---------------------------------------------------------------------------
// RoPE in-place on Q/K fp32, plus bf16 hi/lo outputs for the MMA GEMMs.
// ---------------------------------------------------------------------------
__global__ void rope_qk_kernel(float* __restrict__ Q, float* __restrict__ K,
                               const float* __restrict__ cosT,
                               const float* __restrict__ sinT,
                               __nv_bfloat16* __restrict__ Qh, __nv_bfloat16* __restrict__ Ql,
                               __nv_bfloat16* __restrict__ Kh, __nv_bfloat16* __restrict__ Kl)
{
    long long idx = (long long)blockIdx.x * blockDim.x + threadIdx.x;
    const long long total = (long long)NB * NS * NH * (NHD / 2);
    if (idx >= total) return;
    int d2 = (int)(idx & (NHD / 2 - 1));
    long long r = idx >> 6;
    int h = (int)(r & (NH - 1));
    r >>= 5;
    int s = (int)(r & (NS - 1));
    int b = (int)(r >> 11);

    float cv = cosT[s * (NHD / 2) + d2];
    float sn = sinT[s * (NHD / 2) + d2];
    long long off = ((((long long)b * NS + s) * NH + h) * NHD) + 2 * d2;

    float2 q = *(float2*)(Q + off);
    float2 k = *(float2*)(K + off);
    float2 qo, ko;
    qo.x = q.x * cv - q.y * sn;
    qo.y = q.x * sn + q.y * cv;
    ko.x = k.x * cv - k.y * sn;
    ko.y = k.x * sn + k.y * cv;
    *(float2*)(Q + off) = qo;
    *(float2*)(K + off) = ko;

    __nv_bfloat16 hb, lb;
    split2(qo.x, hb, lb); Qh[off] = hb; Ql[off] = lb;
    split2(qo.y, hb, lb); Qh[off + 1] = hb; Ql[off + 1] = lb;
    split2(ko.x, hb, lb); Kh[off] = hb; Kl[off] = lb;
    split2(ko.y, hb, lb); Kh[off + 1] = hb; Kl[off + 1] = lb;
}

// ---------------------------------------------------------------------------
// Adapter projections (tiny, fp32 SIMT)
// ---------------------------------------------------------------------------
__global__ void adapter_gemm_kernel(const float* __restrict__ adapter,
                                    const float* __restrict__ Wk,
                                    const float* __restrict__ Wv,
                                    float* __restrict__ ak,
                                    float* __restrict__ av)
{
    const int n = blockIdx.x * 256 + threadIdx.x;
    __shared__ float a_sh[NAL][64];
    float accK[NAL], accV[NAL];
#pragma unroll
    for (int r = 0; r < NAL; r++) { accK[r] = 0.f; accV[r] = 0.f; }

    for (int k0 = 0; k0 < ND; k0 += 64) {
        for (int idx = threadIdx.x; idx < NAL * 64; idx += 256) {
            int r = idx / 64, cix = idx % 64;
            a_sh[r][cix] = adapter[r * ND + k0 + cix];
        }
        __syncthreads();
        for (int kc = 0; kc < 64; kc++) {
            float bk = Wk[(long long)(k0 + kc) * ND + n];
            float bv = Wv[(long long)(k0 + kc) * ND + n];
#pragma unroll
            for (int r = 0; r < NAL; r++) {
                accK[r] = fmaf(a_sh[r][kc], bk, accK[r]);
                accV[r] = fmaf(a_sh[r][kc], bv, accV[r]);
            }
        }
        __syncthreads();
    }
#pragma unroll
    for (int r = 0; r < NAL; r++) {
        ak[r * ND + n] = accK[r];
        av[r * ND + n] = accV[r];
    }
}

// ---------------------------------------------------------------------------
// Row softmax -> bf16 hi/lo P
// ---------------------------------------------------------------------------
__global__ void softmax_rows_kernel(const float* __restrict__ sc,
                                    __nv_bfloat16* __restrict__ ph,
                                    __nv_bfloat16* __restrict__ pl)
{
    long long row = blockIdx.x;
    const float* p = sc + row * (long long)NS;
    const int t = threadIdx.x;

    float v[8];
#pragma unroll
    for (int i = 0; i < 8; i++) v[i] = p[t + i * 256];

    float m = -1e30f;
#pragma unroll
    for (int i = 0; i < 8; i++) m = fmaxf(m, v[i]);

    __shared__ float red[256];
    red[t] = m;
    __syncthreads();
    for (int s = 128; s > 0; s >>= 1) {
        if (t < s) red[t] = fmaxf(red[t], red[t + s]);
        __syncthreads();
    }
    m = red[0];
    __syncthreads();

    float sum = 0.f;
#pragma unroll
    for (int i = 0; i < 8; i++) {
        v[i] = __expf(v[i] - m);
        sum += v[i];
    }
    red[t] = sum;
    __syncthreads();
    for (int s = 128; s > 0; s >>= 1) {
        if (t < s) red[t] += red[t + s];
        __syncthreads();
    }
    const float inv = 1.0f / red[0];

    long long base = row * (long long)NS;
#pragma unroll
    for (int i = 0; i < 8; i++) {
        float pv = v[i] * inv;
        __nv_bfloat16 hb, lb;
        split2(pv, hb, lb);
        ph[base + t + i * 256] = hb;
        pl[base + t + i * 256] = lb;
    }
}

// ---------------------------------------------------------------------------
// Adapter attention add (gated), fp32, uses fp32 Q
// ---------------------------------------------------------------------------
__global__ void adapter_attn_kernel(float* __restrict__ AO,
                                    const float* __restrict__ Q,
                                    const float* __restrict__ ak,
                                    const float* __restrict__ av,
                                    const float* __restrict__ gate)
{
    const int h = blockIdx.y;
    const int b = blockIdx.z;
    const int lane = threadIdx.x & 31;
    const int w = threadIdx.x >> 5;
    const int q = blockIdx.x * 8 + w;
    const float inv_sqrt = 0.08838834764831845f;

    const float* qp = Q + (((long long)(b * NS + q)) * NH + h) * NHD;
    float qv[4];
#pragma unroll
    for (int i = 0; i < 4; i++) qv[i] = qp[lane + 32 * i];

    float sc[NAL];
#pragma unroll
    for (int j = 0; j < NAL; j++) {
        const float* akp = ak + j * ND + h * NHD;
        float s = 0.f;
#pragma unroll
        for (int i = 0; i < 4; i++) s = fmaf(qv[i], akp[lane + 32 * i], s);
#pragma unroll
        for (int off = 16; off > 0; off >>= 1)
            s += __shfl_xor_sync(0xFFFFFFFFu, s, off);
        sc[j] = s * inv_sqrt;
    }

    float m = sc[0];
#pragma unroll
    for (int j = 1; j < NAL; j++) m = fmaxf(m, sc[j]);
    float sum = 0.f;
#pragma unroll
    for (int j = 0; j < NAL; j++) {
        sc[j] = __expf(sc[j] - m);
        sum += sc[j];
    }
    const float g = gate[h] / sum;

    float o[4] = {0.f, 0.f, 0.f, 0.f};
#pragma unroll
    for (int j = 0; j < NAL; j++) {
        const float* avp = av + j * ND + h * NHD;
#pragma unroll
        for (int i = 0; i < 4; i++) o[i] = fmaf(sc[j], avp[lane + 32 * i], o[i]);
    }

    float* aop = AO + (((long long)(b * NS + q)) * NH + h) * NHD;
#pragma unroll
    for (int i = 0; i < 4; i++) aop[lane + 32 * i] += g * o[i];
}

// ---------------------------------------------------------------------------
// Launch sequence
// ---------------------------------------------------------------------------
extern "C" void kernel_launch(void* const* d_in, const int* in_sizes, int n_in,
                              void* d_out, int out_size)
{
    const float* x       = (const float*)d_in[0];
    const float* cosT    = (const float*)d_in[1];
    const float* sinT    = (const float*)d_in[2];
    const float* mask    = (const float*)d_in[3];
    const float* wq      = (const float*)d_in[4];
    const float* wk      = (const float*)d_in[5];
    const float* wv      = (const float*)d_in[6];
    const float* wo      = (const float*)d_in[7];
    const float* gate    = (const float*)d_in[8];
    const float* adapter = (const float*)d_in[9];
    float* out = (float*)d_out;

    float *Qp, *Kp, *AOp, *Sc, *akp, *avp;
    __nv_bfloat16 *xh, *xl, *Qh, *Ql, *Kh, *Kl, *Vth, *Vtl, *Ph, *Pl, *AOh, *AOl;
    __nv_bfloat16 *wqh, *wql, *wkh, *wkl, *wvh, *wvl, *woh, *wol;
    cudaGetSymbolAddress((void**)&Qp, g_Q);
    cudaGetSymbolAddress((void**)&Kp, g_K);
    cudaGetSymbolAddress((void**)&AOp, g_AO);
    cudaGetSymbolAddress((void**)&Sc, g_scores);
    cudaGetSymbolAddress((void**)&akp, g_ak);
    cudaGetSymbolAddress((void**)&avp, g_av);
    cudaGetSymbolAddress((void**)&xh, g_xh);
    cudaGetSymbolAddress((void**)&xl, g_xl);
    cudaGetSymbolAddress((void**)&Qh, g_Qh);
    cudaGetSymbolAddress((void**)&Ql, g_Ql);
    cudaGetSymbolAddress((void**)&Kh, g_Kh);
    cudaGetSymbolAddress((void**)&Kl, g_Kl);
    cudaGetSymbolAddress((void**)&Vth, g_Vth);
    cudaGetSymbolAddress((void**)&Vtl, g_Vtl);
    cudaGetSymbolAddress((void**)&Ph, g_Ph);
    cudaGetSymbolAddress((void**)&Pl, g_Pl);
    cudaGetSymbolAddress((void**)&AOh, g_AOh);
    cudaGetSymbolAddress((void**)&AOl, g_AOl);
    cudaGetSymbolAddress((void**)&wqh, g_wqh);
    cudaGetSymbolAddress((void**)&wql, g_wql);
    cudaGetSymbolAddress((void**)&wkh, g_wkh);
    cudaGetSymbolAddress((void**)&wkl, g_wkl);
    cudaGetSymbolAddress((void**)&wvh, g_wvh);
    cudaGetSymbolAddress((void**)&wvl, g_wvl);
    cudaGetSymbolAddress((void**)&woh, g_woh);
    cudaGetSymbolAddress((void**)&wol, g_wol);

    const float inv_sqrt = 0.08838834764831845f;
    const long long NTOK = (long long)NB * NS;          // 4096
    const long long NELT = NTOK * ND;                   // 16M

    // 0. Split x; transpose+split weights
    split_kernel<<<(unsigned)(NELT / 1024), 256>>>(x, xh, xl, NELT);
    {
        dim3 g(ND / 32, ND / 32), b(32, 8);
        wsplit_t_kernel<<<g, b>>>(wq, wqh, wql);
        wsplit_t_kernel<<<g, b>>>(wk, wkh, wkl);
        wsplit_t_kernel<<<g, b>>>(wv, wvh, wvl);
        wsplit_t_kernel<<<g, b>>>(wo, woh, wol);
    }

    // 1-3. Projections (M=4096, N=4096, K=4096)
    {
        dim3 g(ND / BN, (unsigned)(NTOK / BM), 1);
        mma_gemm<0><<<g, 256>>>(xh, xl, wqh, wql, Qp, ND, ND, ND, ND, 1,
                                0, 0, 0, 0, 0, 0, 1.f, nullptr, nullptr, nullptr);
        mma_gemm<0><<<g, 256>>>(xh, xl, wkh, wkl, Kp, ND, ND, ND, ND, 1,
                                0, 0, 0, 0, 0, 0, 1.f, nullptr, nullptr, nullptr);
        mma_gemm<2><<<g, 256>>>(xh, xl, wvh, wvl, nullptr, ND, ND, ND, ND, 1,
                                0, 0, 0, 0, 0, 0, 1.f, nullptr, Vth, Vtl);
    }

    // 4. RoPE (fp32 in-place + bf16 hi/lo out)
    {
        const long long total = (long long)NB * NS * NH * (NHD / 2);
        rope_qk_kernel<<<(unsigned)((total + 255) / 256), 256>>>(
            Qp, Kp, cosT, sinT, Qh, Ql, Kh, Kl);
    }

    // 5. Adapter projections (fp32)
    adapter_gemm_kernel<<<ND / 256, 256>>>(adapter, wk, wv, akp, avp);

    // 6. Scores = Q K^T * inv_sqrt + mask  (per (b,h): M=N=2048, K=128)
    {
        dim3 g(NS / BN, NS / BM, NB * NH);
        mma_gemm<1><<<g, 256>>>(
            Qh, Ql, Kh, Kl, Sc, NHD, ND, ND, NS, NH,
            (long long)NS * ND, (long long)NHD,
            (long long)NS * ND, (long long)NHD,
            (long long)NH * NS * NS, (long long)NS * NS,
            inv_sqrt, mask, nullptr, nullptr);
    }

    // 7. Softmax -> bf16 hi/lo P
    softmax_rows_kernel<<<NB * NH * NS, 256>>>(Sc, Ph, Pl);

    // 8. AO = P @ V  (per (b,h): M=2048, N=128, K=2048; B = V^T[n=d][k=s])
    {
        dim3 g(NHD / BN, NS / BM, NB * NH);
        mma_gemm<0><<<g, 256>>>(
            Ph, Pl, Vth, Vtl, AOp, NS, NS, NS, ND, NH,
            (long long)NH * NS * NS, (long long)NS * NS,
            (long long)NH * NHD * NS, (long long)NHD * NS,
            (long long)NS * ND, (long long)NHD,
            1.f, nullptr, nullptr, nullptr);
    }

    // 9. Adapter attention add (fp32)
    adapter_attn_kernel<<<dim3(NS / 8, NH, NB), 256>>>(AOp, Qp, akp, avp, gate);

    // 10. Split AO; out = AO @ wo
    split_kernel<<<(unsigned)(NELT / 1024), 256>>>(AOp, AOh, AOl, NELT);
    {
        dim3 g(ND / BN, (unsigned)(NTOK / BM), 1);
        mma_gemm<0><<<g, 256>>>(AOh, AOl, woh, wol, out, ND, ND, ND, ND, 1,
                                0, 0, 0, 0, 0, 0, 1.f, nullptr, nullptr, nullptr);
    }
}